// round 14
// baseline (speedup 1.0000x reference)
#include <cuda_runtime.h>
#include <cstdint>

// MultiGaussianReadoutLayer fused kernel, R12.
// B=32, O=12000, F_IN=64, F_OUT=4, M=16.
//
// R12 = R11 mainloop (warp=o, half-split lanes: lane=(half,bp) covering
// b=bp,bp+16; FFMA2; 12 wf/warp/f) with SMALLER CTAs for phase overlap:
// OB=4, NT=128, smem ~31KB -> 6 resident CTAs/SM. Same 24 warps/SM as R11
// but 6 independently-phased CTAs so L1-heavy mainloop and DRAM-heavy eps
// phases of different CTAs overlap instead of alternating.

#define B_    32
#define O_    12000
#define FIN   64
#define M_    16
#define OB    4
#define NT    128
#define FQ    16            // f per staged chunk (4 chunks, 4 syncs)
#define NQ    (FIN / FQ)    // 4
#define XSTR  161           // f-row stride; addressing b*5+o (5 coprime 32 -> conflict-free)
#define EX_BS 84            // exchange b-stride (floats), 8B-aligned
#define EX_OS 20            // exchange o-stride (floats)

#define SW_OFF 0
#define MW_OFF (OB * 1024)                       // 4096
#define SB_OFF (MW_OFF + OB * 256)               // 5120
#define MB_OFF (SB_OFF + OB * 16)                // 5184
#define SX_OFF (MB_OFF + OB * 4)                 // 5200
#define SMEM_FLOATS (SX_OFF + FQ * XSTR)         // 7776 floats = 31104 B

__device__ __forceinline__ uint64_t pack2(float lo, float hi) {
    uint64_t r; asm("mov.b64 %0, {%1,%2};" : "=l"(r) : "f"(lo), "f"(hi)); return r;
}
__device__ __forceinline__ uint64_t ffma2(uint64_t a, uint64_t b, uint64_t c) {
    uint64_t d; asm("fma.rn.f32x2 %0, %1, %2, %3;" : "=l"(d) : "l"(a), "l"(b), "l"(c));
    return d;
}
__device__ __forceinline__ void unpack2(uint64_t v, float& lo, float& hi) {
    asm("mov.b64 {%0,%1}, %2;" : "=f"(lo), "=f"(hi) : "l"(v));
}

__global__ void __launch_bounds__(NT, 6)
mgr_kernel(const float* __restrict__ x,
           const float* __restrict__ mu_w,
           const float* __restrict__ mu_b,
           const float* __restrict__ sigma_w,
           const float* __restrict__ sigma_b,
           const float* __restrict__ eps,
           float* __restrict__ out)
{
    extern __shared__ __align__(16) float smem[];
    float* sw = smem + SW_OFF;
    float* mw = smem + MW_OFF;
    float* sb = smem + SB_OFF;
    float* mb = smem + MB_OFF;
    float* sx = smem + SX_OFF;

    const int tid    = threadIdx.x;
    const int o_base = blockIdx.x * OB;

    // ---- stage weights + biases (coalesced float4, linear smem) ----
    {
        const float4* src_s = (const float4*)(sigma_w + (size_t)o_base * 1024);
        #pragma unroll
        for (int i = tid; i < OB * 256; i += NT)
            ((float4*)sw)[i] = src_s[i];
        const float4* src_m = (const float4*)(mu_w + (size_t)o_base * 256);
        #pragma unroll
        for (int i = tid; i < OB * 64; i += NT)
            ((float4*)mw)[i] = src_m[i];
        if (tid < OB * 16) sb[tid] = sigma_b[(size_t)o_base * 16 + tid];
        if (tid < OB * 4)  mb[tid] = mu_b[(size_t)o_base * 4 + tid];
    }

    // mainloop mapping: warp <-> instance; lane = (output-half, b-pair)
    const int o_w  = tid >> 5;         // 0..3
    const int lane = tid & 31;
    const int half = lane >> 4;        // 0: sig[0..7]+mu[0,1]; 1: sig[8..15]+mu[2,3]
    const int bp   = lane & 15;        // covers b = bp and b = bp+16

    const float* swp = sw + o_w * 1024 + half * 8;
    const float* mwp = mw + o_w * 256 + half * 2;

    uint64_t s0[4], s1[4], m0, m1;

    // ---- mainloop: 4 staged chunks of FQ=16 f-values ----
    #pragma unroll
    for (int q = 0; q < NQ; q++) {
        // stage x chunk transposed: sx[f_local*XSTR + b*5 + o], coalesced LDG
        #pragma unroll
        for (int i = tid; i < B_ * OB * (FQ / 4); i += NT) {   // 512 float4
            int bb  = i >> 4;          // 16 float4 per b (4 o x 4 f4)
            int r   = i & 15;
            int o   = r >> 2;
            int f4l = r & 3;
            float4 v = ((const float4*)x)[((size_t)bb * O_ + o_base + o) * 16 + q * 4 + f4l];
            float* dst = sx + (f4l * 4) * XSTR + bb * 5 + o;
            dst[0]        = v.x;
            dst[XSTR]     = v.y;
            dst[2 * XSTR] = v.z;
            dst[3 * XSTR] = v.w;
        }
        __syncthreads();

        if (q == 0) {   // init AFTER first sync: sb/mb visible (keep R11 race fix)
            #pragma unroll
            for (int j = 0; j < 4; j++) {
                uint64_t v = pack2(sb[o_w * 16 + half * 8 + 2 * j],
                                   sb[o_w * 16 + half * 8 + 2 * j + 1]);
                s0[j] = v; s1[j] = v;
            }
            m0 = pack2(mb[o_w * 4 + 2 * half], mb[o_w * 4 + 2 * half + 1]);
            m1 = m0;
        }

        #pragma unroll
        for (int fl = 0; fl < FQ; fl++) {
            const int f = q * FQ + fl;
            const float xa = sx[fl * XSTR + bp * 5 + o_w];          // conflict-free
            const float xc = sx[fl * XSTR + (bp + 16) * 5 + o_w];
            const uint64_t xx0 = pack2(xa, xa);
            const uint64_t xx1 = pack2(xc, xc);

            ulonglong2 sA = *(const ulonglong2*)(swp + f * 16);      // sig h*8+0..3
            ulonglong2 sB = *(const ulonglong2*)(swp + f * 16 + 4);  // sig h*8+4..7
            uint64_t   mm = *(const uint64_t*)(mwp + f * 4);         // mu 2h,2h+1

            s0[0] = ffma2(sA.x, xx0, s0[0]);
            s0[1] = ffma2(sA.y, xx0, s0[1]);
            s0[2] = ffma2(sB.x, xx0, s0[2]);
            s0[3] = ffma2(sB.y, xx0, s0[3]);
            m0    = ffma2(mm,   xx0, m0);

            s1[0] = ffma2(sA.x, xx1, s1[0]);
            s1[1] = ffma2(sA.y, xx1, s1[1]);
            s1[2] = ffma2(sB.x, xx1, s1[2]);
            s1[3] = ffma2(sB.y, xx1, s1[3]);
            m1    = ffma2(mm,   xx1, m1);
        }
        __syncthreads();
    }

    // ---- exchange sig/mu through smem (reuse dead sigma_w/mu_w region) ----
    // slot layout per (b,o): uint64[0..7] = sig pairs, [8] = mu01, [9] = mu23
    {
        uint64_t* ex0 = (uint64_t*)(sw + bp * EX_BS + o_w * EX_OS);
        uint64_t* ex1 = (uint64_t*)(sw + (bp + 16) * EX_BS + o_w * EX_OS);
        #pragma unroll
        for (int j = 0; j < 4; j++) {
            ex0[half * 4 + j] = s0[j];
            ex1[half * 4 + j] = s1[j];
        }
        ex0[8 + half] = m0;
        ex1[8 + half] = m1;
    }
    __syncthreads();

    const int o_l = tid & (OB - 1);    // 0..3
    const int b   = tid >> 2;          // 0..31
    const int og  = o_base + o_l;

    float sig[16], mu0, mu1, mu2, mu3;
    {
        const uint64_t* exr = (const uint64_t*)(sw + b * EX_BS + o_l * EX_OS);
        #pragma unroll
        for (int j = 0; j < 8; j++)
            unpack2(exr[j], sig[2 * j], sig[2 * j + 1]);
        unpack2(exr[8], mu0, mu1);
        unpack2(exr[9], mu2, mu3);
    }

    uint64_t ep01[4], ep23[4];
    #pragma unroll
    for (int f = 0; f < 4; f++) {
        ep01[f] = pack2(sig[f],     sig[4 + f]);
        ep23[f] = pack2(sig[8 + f], sig[12 + f]);
    }
    const uint64_t mu01 = pack2(mu0, mu1);
    const uint64_t mu23 = pack2(mu2, mu3);

    // ---- eps application: [M, B, O, 4]; per-warp 8 x 64B-aligned chunks ----
    const size_t beo = (size_t)b * O_ + og;
    #pragma unroll
    for (int m = 0; m < M_; m++) {
        const size_t idx = ((size_t)m * B_ * O_ + beo) * 4;
        float4 e = __ldg((const float4*)(eps + idx));
        uint64_t ex = pack2(e.x, e.x), ey = pack2(e.y, e.y);
        uint64_t ez = pack2(e.z, e.z), ew = pack2(e.w, e.w);

        uint64_t p01 = ffma2(ep01[0], ex, mu01);
        p01 = ffma2(ep01[1], ey, p01);
        p01 = ffma2(ep01[2], ez, p01);
        p01 = ffma2(ep01[3], ew, p01);

        uint64_t p23 = ffma2(ep23[0], ex, mu23);
        p23 = ffma2(ep23[1], ey, p23);
        p23 = ffma2(ep23[2], ez, p23);
        p23 = ffma2(ep23[3], ew, p23);

        float4 r;
        unpack2(p01, r.x, r.y);
        unpack2(p23, r.z, r.w);
        *(float4*)(out + idx) = r;
    }
}

extern "C" void kernel_launch(void* const* d_in, const int* in_sizes, int n_in,
                              void* d_out, int out_size)
{
    const float* x       = (const float*)d_in[0];
    const float* mu_w    = (const float*)d_in[1];
    const float* mu_b    = (const float*)d_in[2];
    const float* sigma_w = (const float*)d_in[3];
    const float* sigma_b = (const float*)d_in[4];
    const float* eps     = (const float*)d_in[5];
    float* out           = (float*)d_out;

    const int smem_bytes = SMEM_FLOATS * sizeof(float);   // 31104
    cudaFuncSetAttribute(mgr_kernel,
                         cudaFuncAttributeMaxDynamicSharedMemorySize, smem_bytes);

    dim3 grid(O_ / OB);   // 3000 CTAs
    dim3 block(NT);
    mgr_kernel<<<grid, block, smem_bytes>>>(x, mu_w, mu_b, sigma_w, sigma_b, eps, out);
}